// round 1
// baseline (speedup 1.0000x reference)
#include <cuda_runtime.h>
#include <cstdint>

typedef unsigned long long ull;

#define NPIX 8192
#define NPTS 8192
#define NTOK 16384
#define NWIN 128
#define CAP  256

// ---------------- scratch (device globals; no allocation) ----------------
__device__ float g_Aimg[NPIX * 256];     // image transposed to [pixel][c_in]
__device__ float g_feat[NTOK * 128];     // concat(pix_feat, pts_feat)
__device__ float g_qkv [NTOK * 384];
__device__ float g_o   [NPIX * 128];     // attention output (pixel queries only)
__device__ float g_img [NPIX * 128];     // proj output
__device__ float g_res [NPIX * 128];     // ode output + img
__device__ float g_co  [NPIX * 256];     // conv_out result (row-major)
__device__ float g_wci [256 * 128];      // transposed weights: [K][N]
__device__ float g_wqkv[128 * 384];
__device__ float g_wpr [128 * 128];
__device__ float g_wode[128 * 128];
__device__ float g_wco [128 * 256];
__device__ int   g_ptw [NPTS];
__device__ int   g_win_tok[NWIN * CAP];
__device__ int   g_win_cnt[NWIN];

// ---------------- packed f32x2 helpers ----------------
__device__ __forceinline__ ull pack2(float lo, float hi) {
    ull r; asm("mov.b64 %0, {%1,%2};" : "=l"(r) : "f"(lo), "f"(hi)); return r;
}
__device__ __forceinline__ ull ffma2(ull a, ull b, ull c) {
    ull d; asm("fma.rn.f32x2 %0, %1, %2, %3;" : "=l"(d) : "l"(a), "l"(b), "l"(c)); return d;
}
__device__ __forceinline__ float2 unpack2(ull v) {
    float2 f; asm("mov.b64 {%0,%1}, %2;" : "=f"(f.x), "=f"(f.y) : "l"(v)); return f;
}

// ---------------- weight transpose: src[N][K] -> dst[K][N] ----------------
__global__ void transpose_w(const float* __restrict__ src, float* __restrict__ dst, int N, int K) {
    int i = blockIdx.x * 256 + threadIdx.x;
    if (i < N * K) {
        int k = i % K, n = i / K;
        dst[k * N + n] = src[i];
    }
}

// ---------------- image transpose: in[b][c][hw] -> out[(b*4096+hw)][c] ----------------
__global__ void transpose_img_k(const float* __restrict__ in, float* __restrict__ out) {
    __shared__ float tile[32][33];
    int b = blockIdx.z, c0 = blockIdx.y << 5, hw0 = blockIdx.x << 5;
    int tx = threadIdx.x, ty = threadIdx.y;
    for (int i = ty; i < 32; i += 8)
        tile[i][tx] = in[(size_t)b * 1048576 + (size_t)(c0 + i) * 4096 + hw0 + tx];
    __syncthreads();
    for (int i = ty; i < 32; i += 8)
        out[(size_t)(b * 4096 + hw0 + i) * 256 + c0 + tx] = tile[tx][i];
}

// ---------------- output transpose: in[(b*4096+hw)][c] -> out[b][c][hw] ----------------
__global__ void transpose_out_k(const float* __restrict__ in, float* __restrict__ out) {
    __shared__ float tile[32][33];
    int b = blockIdx.z, c0 = blockIdx.y << 5, hw0 = blockIdx.x << 5;
    int tx = threadIdx.x, ty = threadIdx.y;
    for (int i = ty; i < 32; i += 8)
        tile[i][tx] = in[(size_t)(b * 4096 + hw0 + i) * 256 + c0 + tx];
    __syncthreads();
    for (int i = ty; i < 32; i += 8)
        out[(size_t)b * 1048576 + (size_t)(c0 + i) * 4096 + hw0 + tx] = tile[tx][i];
}

// ---------------- generic GEMM: C[M][N] = A[M][K] @ Bt[K][N] + bias ----------------
// 64x64 tile, BK=16, 256 threads, 4x4 per thread via packed f32x2 FMA.
__global__ __launch_bounds__(256) void gemm64(const float* __restrict__ A,
                                              const float* __restrict__ Bt,
                                              const float* __restrict__ bias,
                                              float* __restrict__ C, int N, int K) {
    __shared__ __align__(16) float sA[16][64];
    __shared__ __align__(16) float sB[16][64];
    const int t = threadIdx.x;
    const int tx = t & 15, ty = t >> 4;
    const int row0 = blockIdx.y << 6, col0 = blockIdx.x << 6;
    const int ar = t >> 2, ak4 = (t & 3) << 2;   // A tile load: 64 rows x 16 k
    const int bk = ty, bn4 = tx << 2;            // B tile load: 16 k x 64 n

    ull acc[4][2];
#pragma unroll
    for (int m = 0; m < 4; m++) { acc[m][0] = 0ull; acc[m][1] = 0ull; }

    for (int k0 = 0; k0 < K; k0 += 16) {
        float4 av = *(const float4*)(A + (size_t)(row0 + ar) * K + k0 + ak4);
        sA[ak4 + 0][ar] = av.x; sA[ak4 + 1][ar] = av.y;
        sA[ak4 + 2][ar] = av.z; sA[ak4 + 3][ar] = av.w;
        *(float4*)&sB[bk][bn4] = *(const float4*)(Bt + (size_t)(k0 + bk) * N + col0 + bn4);
        __syncthreads();
#pragma unroll
        for (int kk = 0; kk < 16; kk++) {
            float4 a4 = *(const float4*)&sA[kk][ty << 2];
            ulonglong2 b2 = *(const ulonglong2*)&sB[kk][tx << 2];
            ull ap;
            ap = pack2(a4.x, a4.x); acc[0][0] = ffma2(ap, b2.x, acc[0][0]); acc[0][1] = ffma2(ap, b2.y, acc[0][1]);
            ap = pack2(a4.y, a4.y); acc[1][0] = ffma2(ap, b2.x, acc[1][0]); acc[1][1] = ffma2(ap, b2.y, acc[1][1]);
            ap = pack2(a4.z, a4.z); acc[2][0] = ffma2(ap, b2.x, acc[2][0]); acc[2][1] = ffma2(ap, b2.y, acc[2][1]);
            ap = pack2(a4.w, a4.w); acc[3][0] = ffma2(ap, b2.x, acc[3][0]); acc[3][1] = ffma2(ap, b2.y, acc[3][1]);
        }
        __syncthreads();
    }
    float4 bv = *(const float4*)(bias + col0 + (tx << 2));
#pragma unroll
    for (int m = 0; m < 4; m++) {
        float2 p0 = unpack2(acc[m][0]);
        float2 p1 = unpack2(acc[m][1]);
        float4 outv = make_float4(p0.x + bv.x, p0.y + bv.y, p1.x + bv.z, p1.y + bv.w);
        *(float4*)(C + (size_t)(row0 + (ty << 2) + m) * N + col0 + (tx << 2)) = outv;
    }
}

// ---------------- point window ids ----------------
__global__ void pt_wid_kernel(const int* __restrict__ uv) {
    int i = blockIdx.x * 256 + threadIdx.x;
    if (i < NPTS) {
        int b = uv[3 * i] & 1;        // % B (B=2), values nonneg
        int u = uv[3 * i + 1] & 63;   // % 64
        int v = uv[3 * i + 2] & 63;   // % 64
        g_ptw[i] = ((b * 8 + (v >> 3)) << 3) + (u >> 3);
    }
}

// ---------------- deterministic window build (1 warp per window) ----------------
__global__ void win_build_kernel() {
    int gtid = blockIdx.x * blockDim.x + threadIdx.x;
    int w = gtid >> 5;
    int lane = gtid & 31;
    if (w >= NWIN) return;
    int b = w >> 6, wy = (w >> 3) & 7, wx = w & 7;
    // pixel tokens first (stable-sort order: original index ascending)
    for (int r = lane; r < 64; r += 32) {
        int v = wy * 8 + (r >> 3), u = wx * 8 + (r & 7);
        g_win_tok[w * CAP + r] = b * 4096 + v * 64 + u;
    }
    // point tokens: warp-ballot scan preserves index order deterministically
    int base = 64;
    for (int i0 = 0; i0 < NPTS; i0 += 32) {
        int i = i0 + lane;
        bool match = (g_ptw[i] == w);
        unsigned mk = __ballot_sync(0xffffffffu, match);
        if (match) {
            int rank = base + __popc(mk & ((1u << lane) - 1));
            if (rank < CAP) g_win_tok[w * CAP + rank] = NPIX + i;
        }
        base += __popc(mk);
    }
    if (lane == 0) g_win_cnt[w] = base < CAP ? base : CAP;
}

// ---------------- windowed attention: block=(head,window), 64 threads=64 pixel queries ----------------
__global__ __launch_bounds__(64) void attn_kernel(const float* __restrict__ qkv,
                                                  float* __restrict__ o_out) {
    const int h = blockIdx.x, w = blockIdx.y;
    __shared__ float4 sK[CAP][4];
    __shared__ float4 sV[CAP][4];
    const int t = threadIdx.x;
    const int T = g_win_cnt[w];
    const int* wt = &g_win_tok[w * CAP];
    for (int j = t; j < T; j += 64) {
        int tok = wt[j];
        const float4* kp = (const float4*)(qkv + (size_t)tok * 384 + 128 + h * 16);
        const float4* vp = (const float4*)(qkv + (size_t)tok * 384 + 256 + h * 16);
        sK[j][0] = kp[0]; sK[j][1] = kp[1]; sK[j][2] = kp[2]; sK[j][3] = kp[3];
        sV[j][0] = vp[0]; sV[j][1] = vp[1]; sV[j][2] = vp[2]; sV[j][3] = vp[3];
    }
    __syncthreads();
    int qtok = wt[t];  // queries = pixel tokens (slots 0..63)
    const float4* qp = (const float4*)(qkv + (size_t)qtok * 384 + h * 16);
    float4 q0 = qp[0], q1 = qp[1], q2 = qp[2], q3 = qp[3];
    float m = -1e30f, l = 0.f;
    float4 o0 = {0,0,0,0}, o1 = {0,0,0,0}, o2 = {0,0,0,0}, o3 = {0,0,0,0};
    for (int j = 0; j < T; j++) {
        float4 k0 = sK[j][0], k1 = sK[j][1], k2 = sK[j][2], k3 = sK[j][3];
        float s = q0.x*k0.x + q0.y*k0.y + q0.z*k0.z + q0.w*k0.w
                + q1.x*k1.x + q1.y*k1.y + q1.z*k1.z + q1.w*k1.w
                + q2.x*k2.x + q2.y*k2.y + q2.z*k2.z + q2.w*k2.w
                + q3.x*k3.x + q3.y*k3.y + q3.z*k3.z + q3.w*k3.w;
        s *= 0.25f;  // 1/sqrt(hd), hd=16
        float mn = fmaxf(m, s);
        float sc = __expf(m - mn);
        float p  = __expf(s - mn);
        l = l * sc + p;
        float4 v0 = sV[j][0], v1 = sV[j][1], v2 = sV[j][2], v3 = sV[j][3];
        o0.x = o0.x*sc + p*v0.x; o0.y = o0.y*sc + p*v0.y; o0.z = o0.z*sc + p*v0.z; o0.w = o0.w*sc + p*v0.w;
        o1.x = o1.x*sc + p*v1.x; o1.y = o1.y*sc + p*v1.y; o1.z = o1.z*sc + p*v1.z; o1.w = o1.w*sc + p*v1.w;
        o2.x = o2.x*sc + p*v2.x; o2.y = o2.y*sc + p*v2.y; o2.z = o2.z*sc + p*v2.z; o2.w = o2.w*sc + p*v2.w;
        o3.x = o3.x*sc + p*v3.x; o3.y = o3.y*sc + p*v3.y; o3.z = o3.z*sc + p*v3.z; o3.w = o3.w*sc + p*v3.w;
        m = mn;
    }
    float inv = 1.f / l;
    float* op = o_out + (size_t)qtok * 128 + h * 16;
    ((float4*)op)[0] = make_float4(o0.x*inv, o0.y*inv, o0.z*inv, o0.w*inv);
    ((float4*)op)[1] = make_float4(o1.x*inv, o1.y*inv, o1.z*inv, o1.w*inv);
    ((float4*)op)[2] = make_float4(o2.x*inv, o2.y*inv, o2.z*inv, o2.w*inv);
    ((float4*)op)[3] = make_float4(o3.x*inv, o3.y*inv, o3.z*inv, o3.w*inv);
}

// ---------------- fused RK4 ODE: 64 rows per block, W in smem, all 16 evals in-register ----------------
__global__ __launch_bounds__(256, 1) void ode_kernel(const float* __restrict__ img,
                                                     const float* __restrict__ Wt,
                                                     const float* __restrict__ bias,
                                                     float* __restrict__ res) {
    extern __shared__ __align__(16) float sm[];
    float* sW = sm;           // 128*128
    float* sZ = sm + 16384;   // 64*128
    const int t = threadIdx.x;
    const int tc = t & 15, tr = t >> 4;
    const int c0 = tc << 3, r0 = tr << 2;
    const int row0 = blockIdx.x << 6;

    for (int idx = t; idx < 4096; idx += 256)
        ((float4*)sW)[idx] = ((const float4*)Wt)[idx];

    float y[4][8], acc[4][8];
#pragma unroll
    for (int r = 0; r < 4; r++) {
        float4 a = *(const float4*)(img + (size_t)(row0 + r0 + r) * 128 + c0);
        float4 b = *(const float4*)(img + (size_t)(row0 + r0 + r) * 128 + c0 + 4);
        y[r][0]=a.x; y[r][1]=a.y; y[r][2]=a.z; y[r][3]=a.w;
        y[r][4]=b.x; y[r][5]=b.y; y[r][6]=b.z; y[r][7]=b.w;
        *(float4*)&sZ[(r0 + r) * 128 + c0]     = a;
        *(float4*)&sZ[(r0 + r) * 128 + c0 + 4] = b;
    }
    float4 bb0 = *(const float4*)(bias + c0);
    float4 bb1 = *(const float4*)(bias + c0 + 4);
    ull bias2[4] = { pack2(bb0.x, bb0.y), pack2(bb0.z, bb0.w),
                     pack2(bb1.x, bb1.y), pack2(bb1.z, bb1.w) };
    __syncthreads();

    const float zc[3] = {0.125f, 0.125f, 0.25f};   // 0.5*dt, 0.5*dt, dt (dt=0.25)
    const float aw[4] = {1.f, 2.f, 2.f, 1.f};

    for (int step = 0; step < 4; step++) {
#pragma unroll
        for (int st = 0; st < 4; st++) {
            ull ko[4][4];
#pragma unroll
            for (int r = 0; r < 4; r++) {
                ko[r][0] = bias2[0]; ko[r][1] = bias2[1];
                ko[r][2] = bias2[2]; ko[r][3] = bias2[3];
            }
#pragma unroll 2
            for (int i = 0; i < 128; i++) {
                ulonglong2 w0 = *(const ulonglong2*)&sW[i * 128 + c0];
                ulonglong2 w1 = *(const ulonglong2*)&sW[i * 128 + c0 + 4];
#pragma unroll
                for (int r = 0; r < 4; r++) {
                    float zv = sZ[(r0 + r) * 128 + i];
                    ull zp = pack2(zv, zv);
                    ko[r][0] = ffma2(zp, w0.x, ko[r][0]);
                    ko[r][1] = ffma2(zp, w0.y, ko[r][1]);
                    ko[r][2] = ffma2(zp, w1.x, ko[r][2]);
                    ko[r][3] = ffma2(zp, w1.y, ko[r][3]);
                }
            }
            float kf[4][8];
#pragma unroll
            for (int r = 0; r < 4; r++) {
#pragma unroll
                for (int cp = 0; cp < 4; cp++) {
                    float2 p = unpack2(ko[r][cp]);
                    kf[r][2*cp]     = fmaxf(p.x, 0.f);
                    kf[r][2*cp + 1] = fmaxf(p.y, 0.f);
                }
            }
#pragma unroll
            for (int r = 0; r < 4; r++)
#pragma unroll
                for (int c = 0; c < 8; c++)
                    acc[r][c] = (st == 0) ? kf[r][c] : acc[r][c] + aw[st] * kf[r][c];
            __syncthreads();
            if (st < 3) {
#pragma unroll
                for (int r = 0; r < 4; r++)
#pragma unroll
                    for (int c = 0; c < 8; c++)
                        sZ[(r0 + r) * 128 + c0 + c] = y[r][c] + zc[st] * kf[r][c];
            } else {
#pragma unroll
                for (int r = 0; r < 4; r++)
#pragma unroll
                    for (int c = 0; c < 8; c++) {
                        y[r][c] += (1.f / 24.f) * acc[r][c];   // dt/6 = 1/24
                        sZ[(r0 + r) * 128 + c0 + c] = y[r][c];
                    }
            }
            __syncthreads();
        }
    }
#pragma unroll
    for (int r = 0; r < 4; r++) {
        float4 a = *(const float4*)(img + (size_t)(row0 + r0 + r) * 128 + c0);
        float4 b = *(const float4*)(img + (size_t)(row0 + r0 + r) * 128 + c0 + 4);
        float4 oa = make_float4(y[r][0] + a.x, y[r][1] + a.y, y[r][2] + a.z, y[r][3] + a.w);
        float4 ob = make_float4(y[r][4] + b.x, y[r][5] + b.y, y[r][6] + b.z, y[r][7] + b.w);
        *(float4*)(res + (size_t)(row0 + r0 + r) * 128 + c0)     = oa;
        *(float4*)(res + (size_t)(row0 + r0 + r) * 128 + c0 + 4) = ob;
    }
}

// ---------------- launch ----------------
extern "C" void kernel_launch(void* const* d_in, const int* in_sizes, int n_in,
                              void* d_out, int out_size) {
    const float* img   = (const float*)d_in[0];
    const int*   ptsuv = (const int*)  d_in[1];
    const float* ptsf  = (const float*)d_in[2];
    const float* wci   = (const float*)d_in[3];
    const float* bci   = (const float*)d_in[4];
    const float* wqkv  = (const float*)d_in[5];
    const float* bqkv  = (const float*)d_in[6];
    const float* wpr   = (const float*)d_in[7];
    const float* bpr   = (const float*)d_in[8];
    const float* wode  = (const float*)d_in[9];
    const float* bode  = (const float*)d_in[10];
    const float* wco   = (const float*)d_in[11];
    const float* bco   = (const float*)d_in[12];
    float* out = (float*)d_out;

    float *pAimg, *pfeat, *pqkv, *po, *pimg, *pres, *pco;
    float *pwci, *pwqkv, *pwpr, *pwode, *pwco;
    cudaGetSymbolAddress((void**)&pAimg, g_Aimg);
    cudaGetSymbolAddress((void**)&pfeat, g_feat);
    cudaGetSymbolAddress((void**)&pqkv,  g_qkv);
    cudaGetSymbolAddress((void**)&po,    g_o);
    cudaGetSymbolAddress((void**)&pimg,  g_img);
    cudaGetSymbolAddress((void**)&pres,  g_res);
    cudaGetSymbolAddress((void**)&pco,   g_co);
    cudaGetSymbolAddress((void**)&pwci,  g_wci);
    cudaGetSymbolAddress((void**)&pwqkv, g_wqkv);
    cudaGetSymbolAddress((void**)&pwpr,  g_wpr);
    cudaGetSymbolAddress((void**)&pwode, g_wode);
    cudaGetSymbolAddress((void**)&pwco,  g_wco);

    cudaFuncSetAttribute(ode_kernel, cudaFuncAttributeMaxDynamicSharedMemorySize, 98304);

    // weight transposes to [K][N]
    transpose_w<<<(128 * 256 + 255) / 256, 256>>>(wci,  pwci, 128, 256);
    transpose_w<<<(384 * 128 + 255) / 256, 256>>>(wqkv, pwqkv, 384, 128);
    transpose_w<<<64, 256>>>(wpr,  pwpr, 128, 128);
    transpose_w<<<64, 256>>>(wode, pwode, 128, 128);
    transpose_w<<<128, 256>>>(wco, pwco, 256, 128);

    // image -> [pixel][c_in]; points feat -> second half of g_feat
    transpose_img_k<<<dim3(128, 8, 2), dim3(32, 8)>>>(img, pAimg);
    cudaMemcpyAsync(pfeat + (size_t)NPIX * 128, ptsf, (size_t)NPTS * 128 * sizeof(float),
                    cudaMemcpyDeviceToDevice);

    // window build
    pt_wid_kernel<<<32, 256>>>(ptsuv);
    win_build_kernel<<<4, 1024>>>();

    // conv_in: g_feat[0:8192] = Aimg @ wci^T + b
    gemm64<<<dim3(2, 128), 256>>>(pAimg, pwci, bci, pfeat, 128, 256);
    // qkv on all 16384 tokens
    gemm64<<<dim3(6, 256), 256>>>(pfeat, pwqkv, bqkv, pqkv, 384, 128);
    // attention (pixel queries only)
    attn_kernel<<<dim3(8, 128), 64>>>(pqkv, po);
    // proj (image tokens only)
    gemm64<<<dim3(2, 128), 256>>>(po, pwpr, bpr, pimg, 128, 128);
    // fused RK4 ODE + residual
    ode_kernel<<<128, 256, 98304>>>(pimg, pwode, bode, pres);
    // conv_out
    gemm64<<<dim3(4, 128), 256>>>(pres, pwco, bco, pco, 256, 128);
    // scatter to NCHW
    transpose_out_k<<<dim3(128, 8, 2), dim3(32, 8)>>>(pco, out);
}

// round 3
// speedup vs baseline: 1.2869x; 1.2869x over previous
#include <cuda_runtime.h>
#include <cuda_bf16.h>
#include <mma.h>
#include <cstdint>

using namespace nvcuda;

#define NPIX 8192
#define NPTS 8192
#define NTOK 16384
#define NWIN 128
#define CAP  256

// ---------------- scratch (device globals; no allocation) ----------------
__device__ float g_Aimg[NPIX * 256];
__device__ float g_feat[NTOK * 128];
__device__ float g_qkv [NTOK * 384];
__device__ float g_o   [NPIX * 128];
__device__ float g_img [NPIX * 128];
__device__ float g_res [NPIX * 128];
__device__ float g_co  [NPIX * 256];
__device__ __nv_bfloat16 g_wh[147456];   // hi parts: ci|qkv|pr|ode|co
__device__ __nv_bfloat16 g_wl[147456];   // lo parts
__device__ int   g_ptw [NPTS];
__device__ int   g_win_tok[NWIN * CAP];
__device__ int   g_win_cnt[NWIN];

// weight offsets in g_wh/g_wl
#define WOFF_CI  0
#define WOFF_QKV 32768
#define WOFF_PR  81920
#define WOFF_ODE 98304
#define WOFF_CO  114688

// ---------------- bf16 pack helpers ----------------
__device__ __forceinline__ uint32_t bf16x2_of(float hi, float lo) {
    uint32_t r; asm("cvt.rn.bf16x2.f32 %0, %1, %2;" : "=r"(r) : "f"(hi), "f"(lo)); return r;
}
__device__ __forceinline__ float bf16lo_f(uint32_t v) { return __uint_as_float(v << 16); }
__device__ __forceinline__ float bf16hi_f(uint32_t v) { return __uint_as_float(v & 0xffff0000u); }

// ---------------- weight hi/lo split (no transpose needed: B is [N][K]) ----------------
__global__ void split_weights(const float* __restrict__ wci, const float* __restrict__ wqkv,
                              const float* __restrict__ wpr, const float* __restrict__ wode,
                              const float* __restrict__ wco) {
    int i = blockIdx.x * 256 + threadIdx.x;
    if (i >= 147456) return;
    float x;
    if (i < WOFF_QKV)      x = wci [i];
    else if (i < WOFF_PR)  x = wqkv[i - WOFF_QKV];
    else if (i < WOFF_ODE) x = wpr [i - WOFF_PR];
    else if (i < WOFF_CO)  x = wode[i - WOFF_ODE];
    else                   x = wco [i - WOFF_CO];
    __nv_bfloat16 h = __float2bfloat16(x);
    g_wh[i] = h;
    g_wl[i] = __float2bfloat16(x - __bfloat162float(h));
}

// ---------------- image transpose: in[b][c][hw] -> out[(b*4096+hw)][c] ----------------
__global__ void transpose_img_k(const float* __restrict__ in, float* __restrict__ out) {
    __shared__ float tile[32][33];
    int b = blockIdx.z, c0 = blockIdx.y << 5, hw0 = blockIdx.x << 5;
    int tx = threadIdx.x, ty = threadIdx.y;
    for (int i = ty; i < 32; i += 8)
        tile[i][tx] = in[(size_t)b * 1048576 + (size_t)(c0 + i) * 4096 + hw0 + tx];
    __syncthreads();
    for (int i = ty; i < 32; i += 8)
        out[(size_t)(b * 4096 + hw0 + i) * 256 + c0 + tx] = tile[tx][i];
}

__global__ void transpose_out_k(const float* __restrict__ in, float* __restrict__ out) {
    __shared__ float tile[32][33];
    int b = blockIdx.z, c0 = blockIdx.y << 5, hw0 = blockIdx.x << 5;
    int tx = threadIdx.x, ty = threadIdx.y;
    for (int i = ty; i < 32; i += 8)
        tile[i][tx] = in[(size_t)(b * 4096 + hw0 + i) * 256 + c0 + tx];
    __syncthreads();
    for (int i = ty; i < 32; i += 8)
        out[(size_t)b * 1048576 + (size_t)(c0 + i) * 4096 + hw0 + tx] = tile[tx][i];
}

// ============================================================================
// Tensor-core GEMM via wmma bf16 hi/lo split:
//   C[M][N] = A[M][K] @ B[N][K]^T + bias,  A fp32 (split on the fly),
//   B pre-split into Bh/Bl bf16 [N][K].
//   Block tile 128M x 64N, 8 warps (4Mx2N), warp tile 32x32, K-step 16.
// ============================================================================
__global__ __launch_bounds__(256) void bfgemm(const float* __restrict__ A,
                                              const __nv_bfloat16* __restrict__ Bh,
                                              const __nv_bfloat16* __restrict__ Bl,
                                              const float* __restrict__ bias,
                                              float* __restrict__ C, int N, int K) {
    __shared__ __align__(16) __nv_bfloat16 sAh[128 * 16], sAl[128 * 16];
    __shared__ __align__(16) __nv_bfloat16 sBh[64 * 16],  sBl[64 * 16];
    __shared__ __align__(16) float scratch[128 * 64];

    const int t = threadIdx.x;
    const int w = t >> 5;
    const int row0 = blockIdx.y << 7, col0 = blockIdx.x << 6;
    const int wm = w >> 1, wn = w & 1;
    const int m0 = wm << 5, n0 = wn << 5;

    wmma::fragment<wmma::accumulator, 16, 16, 16, float> acc[2][2];
#pragma unroll
    for (int mi = 0; mi < 2; mi++)
#pragma unroll
        for (int ni = 0; ni < 2; ni++)
            wmma::fill_fragment(acc[mi][ni], 0.f);

    const uint32_t* Bh32 = (const uint32_t*)Bh;
    const uint32_t* Bl32 = (const uint32_t*)Bl;
    uint32_t* sBh32 = (uint32_t*)sBh;
    uint32_t* sBl32 = (uint32_t*)sBl;
    uint32_t* sAh32 = (uint32_t*)sAh;
    uint32_t* sAl32 = (uint32_t*)sAl;

    for (int k0 = 0; k0 < K; k0 += 16) {
        // A tile: 128 rows x 16 cols fp32 -> bf16 h/l
#pragma unroll
        for (int i = 0; i < 2; i++) {
            int idx = t + (i << 8);
            int r = idx >> 2, c = (idx & 3) << 2;
            float4 v = *(const float4*)(A + (size_t)(row0 + r) * K + k0 + c);
            uint32_t h01 = bf16x2_of(v.y, v.x);
            uint32_t h23 = bf16x2_of(v.w, v.z);
            uint32_t l01 = bf16x2_of(v.y - bf16hi_f(h01), v.x - bf16lo_f(h01));
            uint32_t l23 = bf16x2_of(v.w - bf16hi_f(h23), v.z - bf16lo_f(h23));
            sAh32[(r << 3) + (c >> 1)]     = h01;
            sAh32[(r << 3) + (c >> 1) + 1] = h23;
            sAl32[(r << 3) + (c >> 1)]     = l01;
            sAl32[(r << 3) + (c >> 1) + 1] = l23;
        }
        // B tile: 64 rows x 16 cols bf16 (pre-split)
#pragma unroll
        for (int i = 0; i < 2; i++) {
            int idx = t + (i << 8);
            int r = idx >> 3, c2 = idx & 7;
            size_t g = (size_t)(col0 + r) * (K >> 1) + (k0 >> 1) + c2;
            sBh32[(r << 3) + c2] = Bh32[g];
            sBl32[(r << 3) + c2] = Bl32[g];
        }
        __syncthreads();

        wmma::fragment<wmma::matrix_a, 16, 16, 16, __nv_bfloat16, wmma::row_major> ah0, ah1, al0, al1;
        wmma::fragment<wmma::matrix_b, 16, 16, 16, __nv_bfloat16, wmma::col_major> bh0, bh1, bl0, bl1;
        wmma::load_matrix_sync(ah0, sAh + (size_t)m0 * 16, 16);
        wmma::load_matrix_sync(ah1, sAh + (size_t)(m0 + 16) * 16, 16);
        wmma::load_matrix_sync(al0, sAl + (size_t)m0 * 16, 16);
        wmma::load_matrix_sync(al1, sAl + (size_t)(m0 + 16) * 16, 16);
        wmma::load_matrix_sync(bh0, sBh + (size_t)n0 * 16, 16);
        wmma::load_matrix_sync(bh1, sBh + (size_t)(n0 + 16) * 16, 16);
        wmma::load_matrix_sync(bl0, sBl + (size_t)n0 * 16, 16);
        wmma::load_matrix_sync(bl1, sBl + (size_t)(n0 + 16) * 16, 16);

        wmma::mma_sync(acc[0][0], ah0, bh0, acc[0][0]);
        wmma::mma_sync(acc[0][1], ah0, bh1, acc[0][1]);
        wmma::mma_sync(acc[1][0], ah1, bh0, acc[1][0]);
        wmma::mma_sync(acc[1][1], ah1, bh1, acc[1][1]);
        wmma::mma_sync(acc[0][0], ah0, bl0, acc[0][0]);
        wmma::mma_sync(acc[0][1], ah0, bl1, acc[0][1]);
        wmma::mma_sync(acc[1][0], ah1, bl0, acc[1][0]);
        wmma::mma_sync(acc[1][1], ah1, bl1, acc[1][1]);
        wmma::mma_sync(acc[0][0], al0, bh0, acc[0][0]);
        wmma::mma_sync(acc[0][1], al0, bh1, acc[0][1]);
        wmma::mma_sync(acc[1][0], al1, bh0, acc[1][0]);
        wmma::mma_sync(acc[1][1], al1, bh1, acc[1][1]);
        __syncthreads();
    }

#pragma unroll
    for (int mi = 0; mi < 2; mi++)
#pragma unroll
        for (int ni = 0; ni < 2; ni++)
            wmma::store_matrix_sync(scratch + (size_t)(m0 + mi * 16) * 64 + n0 + ni * 16,
                                    acc[mi][ni], 64, wmma::mem_row_major);
    __syncthreads();

    // epilogue: bias + store fp32
    int r = t >> 1, c0 = (t & 1) << 5;
#pragma unroll
    for (int q = 0; q < 8; q++) {
        float4 v = *(float4*)(scratch + r * 64 + c0 + q * 4);
        float4 b = *(const float4*)(bias + col0 + c0 + q * 4);
        v.x += b.x; v.y += b.y; v.z += b.z; v.w += b.w;
        *(float4*)(C + (size_t)(row0 + r) * N + col0 + c0 + q * 4) = v;
    }
}

// ---------------- point window ids ----------------
__global__ void pt_wid_kernel(const int* __restrict__ uv) {
    int i = blockIdx.x * 256 + threadIdx.x;
    if (i < NPTS) {
        int b = uv[3 * i] & 1;
        int u = uv[3 * i + 1] & 63;
        int v = uv[3 * i + 2] & 63;
        g_ptw[i] = ((b * 8 + (v >> 3)) << 3) + (u >> 3);
    }
}

// ---------------- deterministic window build (1 warp per window) ----------------
__global__ void win_build_kernel() {
    int gtid = blockIdx.x * blockDim.x + threadIdx.x;
    int w = gtid >> 5;
    int lane = gtid & 31;
    if (w >= NWIN) return;
    int b = w >> 6, wy = (w >> 3) & 7, wx = w & 7;
    for (int r = lane; r < 64; r += 32) {
        int v = wy * 8 + (r >> 3), u = wx * 8 + (r & 7);
        g_win_tok[w * CAP + r] = b * 4096 + v * 64 + u;
    }
    int base = 64;
    for (int i0 = 0; i0 < NPTS; i0 += 32) {
        int i = i0 + lane;
        bool match = (g_ptw[i] == w);
        unsigned mk = __ballot_sync(0xffffffffu, match);
        if (match) {
            int rank = base + __popc(mk & ((1u << lane) - 1));
            if (rank < CAP) g_win_tok[w * CAP + rank] = NPIX + i;
        }
        base += __popc(mk);
    }
    if (lane == 0) g_win_cnt[w] = base < CAP ? base : CAP;
}

// ---------------- windowed attention (fp32, online softmax) ----------------
__global__ __launch_bounds__(64) void attn_kernel(const float* __restrict__ qkv,
                                                  float* __restrict__ o_out) {
    const int h = blockIdx.x, w = blockIdx.y;
    __shared__ float4 sK[CAP][4];
    __shared__ float4 sV[CAP][4];
    const int t = threadIdx.x;
    const int T = g_win_cnt[w];
    const int* wt = &g_win_tok[w * CAP];
    for (int j = t; j < T; j += 64) {
        int tok = wt[j];
        const float4* kp = (const float4*)(qkv + (size_t)tok * 384 + 128 + h * 16);
        const float4* vp = (const float4*)(qkv + (size_t)tok * 384 + 256 + h * 16);
        sK[j][0] = kp[0]; sK[j][1] = kp[1]; sK[j][2] = kp[2]; sK[j][3] = kp[3];
        sV[j][0] = vp[0]; sV[j][1] = vp[1]; sV[j][2] = vp[2]; sV[j][3] = vp[3];
    }
    __syncthreads();
    int qtok = wt[t];
    const float4* qp = (const float4*)(qkv + (size_t)qtok * 384 + h * 16);
    float4 q0 = qp[0], q1 = qp[1], q2 = qp[2], q3 = qp[3];
    float m = -1e30f, l = 0.f;
    float4 o0 = {0,0,0,0}, o1 = {0,0,0,0}, o2 = {0,0,0,0}, o3 = {0,0,0,0};
    for (int j = 0; j < T; j++) {
        float4 k0 = sK[j][0], k1 = sK[j][1], k2 = sK[j][2], k3 = sK[j][3];
        float s = q0.x*k0.x + q0.y*k0.y + q0.z*k0.z + q0.w*k0.w
                + q1.x*k1.x + q1.y*k1.y + q1.z*k1.z + q1.w*k1.w
                + q2.x*k2.x + q2.y*k2.y + q2.z*k2.z + q2.w*k2.w
                + q3.x*k3.x + q3.y*k3.y + q3.z*k3.z + q3.w*k3.w;
        s *= 0.25f;
        float mn = fmaxf(m, s);
        float sc = __expf(m - mn);
        float p  = __expf(s - mn);
        l = l * sc + p;
        float4 v0 = sV[j][0], v1 = sV[j][1], v2 = sV[j][2], v3 = sV[j][3];
        o0.x = o0.x*sc + p*v0.x; o0.y = o0.y*sc + p*v0.y; o0.z = o0.z*sc + p*v0.z; o0.w = o0.w*sc + p*v0.w;
        o1.x = o1.x*sc + p*v1.x; o1.y = o1.y*sc + p*v1.y; o1.z = o1.z*sc + p*v1.z; o1.w = o1.w*sc + p*v1.w;
        o2.x = o2.x*sc + p*v2.x; o2.y = o2.y*sc + p*v2.y; o2.z = o2.z*sc + p*v2.z; o2.w = o2.w*sc + p*v2.w;
        o3.x = o3.x*sc + p*v3.x; o3.y = o3.y*sc + p*v3.y; o3.z = o3.z*sc + p*v3.z; o3.w = o3.w*sc + p*v3.w;
        m = mn;
    }
    float inv = 1.f / l;
    float* op = o_out + (size_t)qtok * 128 + h * 16;
    ((float4*)op)[0] = make_float4(o0.x*inv, o0.y*inv, o0.z*inv, o0.w*inv);
    ((float4*)op)[1] = make_float4(o1.x*inv, o1.y*inv, o1.z*inv, o1.w*inv);
    ((float4*)op)[2] = make_float4(o2.x*inv, o2.y*inv, o2.z*inv, o2.w*inv);
    ((float4*)op)[3] = make_float4(o3.x*inv, o3.y*inv, o3.z*inv, o3.w*inv);
}

// ============================================================================
// Fused RK4 ODE on wmma bf16 hi/lo:
//   128 CTAs x 256 threads; CTA owns 64 rows. W hi/lo resident in smem,
//   z hi/lo rebuilt each eval, y/acc in registers (tid-owned elements),
//   D round-trips through smem scratch to decouple fragment layout.
// SMEM layout (dynamic):
//   [0)       scratch f32 [64][128]          32768
//   [32768)   bias  f32 [128]                  512
//   [33280)   Wh bf16 [128][136]              34816
//   [68096)   Wl bf16 [128][136]              34816
//   [102912)  Zh bf16 [64][136]               17408
//   [120320)  Zl bf16 [64][136]               17408   -> total 137728
// ============================================================================
#define ODE_SMEM 137728

__global__ __launch_bounds__(256, 1) void ode_wmma(const float* __restrict__ img,
                                                   const __nv_bfloat16* __restrict__ Wh_g,
                                                   const __nv_bfloat16* __restrict__ Wl_g,
                                                   const float* __restrict__ bias,
                                                   float* __restrict__ res) {
    extern __shared__ __align__(16) char sm[];
    float* scratch = (float*)sm;
    float* sBias   = (float*)(sm + 32768);
    __nv_bfloat16* sWh = (__nv_bfloat16*)(sm + 33280);
    __nv_bfloat16* sWl = (__nv_bfloat16*)(sm + 68096);
    __nv_bfloat16* sZh = (__nv_bfloat16*)(sm + 102912);
    __nv_bfloat16* sZl = (__nv_bfloat16*)(sm + 120320);

    const int t = threadIdx.x;
    const int w = t >> 5;
    const int row0 = blockIdx.x << 6;

    // load W hi/lo into smem (ld 136)
    const uint32_t* wh32 = (const uint32_t*)Wh_g;
    const uint32_t* wl32 = (const uint32_t*)Wl_g;
    uint32_t* sWh32 = (uint32_t*)sWh;
    uint32_t* sWl32 = (uint32_t*)sWl;
    for (int idx = t; idx < 8192; idx += 256) {
        int n = idx >> 6, c2 = idx & 63;
        sWh32[n * 68 + c2] = wh32[idx];
        sWl32[n * 68 + c2] = wl32[idx];
    }
    if (t < 128) sBias[t] = bias[t];

    // y init (thread owns row r = t>>2, cols c0..c0+31)
    const int r = t >> 2, c0 = (t & 3) << 5;
    float y[32], accv[32];
#pragma unroll
    for (int q = 0; q < 8; q++) {
        float4 v = *(const float4*)(img + (size_t)(row0 + r) * 128 + c0 + q * 4);
        y[q*4] = v.x; y[q*4+1] = v.y; y[q*4+2] = v.z; y[q*4+3] = v.w;
    }
    // initial z = y, split to Zh/Zl
    uint32_t* zh32 = (uint32_t*)(sZh + r * 136 + c0);
    uint32_t* zl32 = (uint32_t*)(sZl + r * 136 + c0);
#pragma unroll
    for (int j = 0; j < 16; j++) {
        float x0 = y[2*j], x1 = y[2*j+1];
        uint32_t h = bf16x2_of(x1, x0);
        zh32[j] = h;
        zl32[j] = bf16x2_of(x1 - bf16hi_f(h), x0 - bf16lo_f(h));
    }
    __syncthreads();

    const int wm = w >> 2, wn = w & 3;
    const int m0 = wm << 5, n0 = wn << 5;

    for (int ev = 0; ev < 16; ev++) {
        // ---- MMA phase ----
        wmma::fragment<wmma::accumulator, 16, 16, 16, float> acc[2][2];
#pragma unroll
        for (int mi = 0; mi < 2; mi++)
#pragma unroll
            for (int ni = 0; ni < 2; ni++)
                wmma::fill_fragment(acc[mi][ni], 0.f);

#pragma unroll
        for (int k = 0; k < 8; k++) {
            wmma::fragment<wmma::matrix_a, 16, 16, 16, __nv_bfloat16, wmma::row_major> ah0, ah1, al0, al1;
            wmma::fragment<wmma::matrix_b, 16, 16, 16, __nv_bfloat16, wmma::col_major> bh0, bh1, bl0, bl1;
            wmma::load_matrix_sync(ah0, sZh + (size_t)m0 * 136 + k * 16, 136);
            wmma::load_matrix_sync(ah1, sZh + (size_t)(m0 + 16) * 136 + k * 16, 136);
            wmma::load_matrix_sync(al0, sZl + (size_t)m0 * 136 + k * 16, 136);
            wmma::load_matrix_sync(al1, sZl + (size_t)(m0 + 16) * 136 + k * 16, 136);
            wmma::load_matrix_sync(bh0, sWh + (size_t)n0 * 136 + k * 16, 136);
            wmma::load_matrix_sync(bh1, sWh + (size_t)(n0 + 16) * 136 + k * 16, 136);
            wmma::load_matrix_sync(bl0, sWl + (size_t)n0 * 136 + k * 16, 136);
            wmma::load_matrix_sync(bl1, sWl + (size_t)(n0 + 16) * 136 + k * 16, 136);

            wmma::mma_sync(acc[0][0], ah0, bh0, acc[0][0]);
            wmma::mma_sync(acc[0][1], ah0, bh1, acc[0][1]);
            wmma::mma_sync(acc[1][0], ah1, bh0, acc[1][0]);
            wmma::mma_sync(acc[1][1], ah1, bh1, acc[1][1]);
            wmma::mma_sync(acc[0][0], ah0, bl0, acc[0][0]);
            wmma::mma_sync(acc[0][1], ah0, bl1, acc[0][1]);
            wmma::mma_sync(acc[1][0], ah1, bl0, acc[1][0]);
            wmma::mma_sync(acc[1][1], ah1, bl1, acc[1][1]);
            wmma::mma_sync(acc[0][0], al0, bh0, acc[0][0]);
            wmma::mma_sync(acc[0][1], al0, bh1, acc[0][1]);
            wmma::mma_sync(acc[1][0], al1, bh0, acc[1][0]);
            wmma::mma_sync(acc[1][1], al1, bh1, acc[1][1]);
        }
#pragma unroll
        for (int mi = 0; mi < 2; mi++)
#pragma unroll
            for (int ni = 0; ni < 2; ni++)
                wmma::store_matrix_sync(scratch + (size_t)(m0 + mi * 16) * 128 + n0 + ni * 16,
                                        acc[mi][ni], 128, wmma::mem_row_major);
        __syncthreads();

        // ---- elementwise RK4 epilogue ----
        const int st = ev & 3;
        const float zc = (st < 2) ? 0.125f : 0.25f;
        const float aw = (st == 1 || st == 2) ? 2.f : 1.f;
#pragma unroll
        for (int j = 0; j < 16; j++) {
            float k0f = fmaxf(scratch[r * 128 + c0 + 2*j]     + sBias[c0 + 2*j],     0.f);
            float k1f = fmaxf(scratch[r * 128 + c0 + 2*j + 1] + sBias[c0 + 2*j + 1], 0.f);
            float a0 = (st == 0) ? k0f : accv[2*j]     + aw * k0f;
            float a1 = (st == 0) ? k1f : accv[2*j + 1] + aw * k1f;
            accv[2*j] = a0; accv[2*j+1] = a1;
            float z0, z1;
            if (st < 3) { z0 = y[2*j] + zc * k0f; z1 = y[2*j+1] + zc * k1f; }
            else {
                y[2*j]   += (1.f / 24.f) * a0;
                y[2*j+1] += (1.f / 24.f) * a1;
                z0 = y[2*j]; z1 = y[2*j+1];
            }
            uint32_t h = bf16x2_of(z1, z0);
            zh32[j] = h;
            zl32[j] = bf16x2_of(z1 - bf16hi_f(h), z0 - bf16lo_f(h));
        }
        __syncthreads();
    }

    // res = y_final + img
#pragma unroll
    for (int q = 0; q < 8; q++) {
        float4 v = *(const float4*)(img + (size_t)(row0 + r) * 128 + c0 + q * 4);
        v.x += y[q*4]; v.y += y[q*4+1]; v.z += y[q*4+2]; v.w += y[q*4+3];
        *(float4*)(res + (size_t)(row0 + r) * 128 + c0 + q * 4) = v;
    }
}

// ---------------- launch ----------------
extern "C" void kernel_launch(void* const* d_in, const int* in_sizes, int n_in,
                              void* d_out, int out_size) {
    const float* img   = (const float*)d_in[0];
    const int*   ptsuv = (const int*)  d_in[1];
    const float* ptsf  = (const float*)d_in[2];
    const float* wci   = (const float*)d_in[3];
    const float* bci   = (const float*)d_in[4];
    const float* wqkv  = (const float*)d_in[5];
    const float* bqkv  = (const float*)d_in[6];
    const float* wpr   = (const float*)d_in[7];
    const float* bpr   = (const float*)d_in[8];
    const float* wode  = (const float*)d_in[9];
    const float* bode  = (const float*)d_in[10];
    const float* wco   = (const float*)d_in[11];
    const float* bco   = (const float*)d_in[12];
    float* out = (float*)d_out;

    float *pAimg, *pfeat, *pqkv, *po, *pimg, *pres, *pco;
    __nv_bfloat16 *pwh, *pwl;
    cudaGetSymbolAddress((void**)&pAimg, g_Aimg);
    cudaGetSymbolAddress((void**)&pfeat, g_feat);
    cudaGetSymbolAddress((void**)&pqkv,  g_qkv);
    cudaGetSymbolAddress((void**)&po,    g_o);
    cudaGetSymbolAddress((void**)&pimg,  g_img);
    cudaGetSymbolAddress((void**)&pres,  g_res);
    cudaGetSymbolAddress((void**)&pco,   g_co);
    cudaGetSymbolAddress((void**)&pwh,   g_wh);
    cudaGetSymbolAddress((void**)&pwl,   g_wl);

    cudaFuncSetAttribute(ode_wmma, cudaFuncAttributeMaxDynamicSharedMemorySize, ODE_SMEM);

    split_weights<<<576, 256>>>(wci, wqkv, wpr, wode, wco);
    transpose_img_k<<<dim3(128, 8, 2), dim3(32, 8)>>>(img, pAimg);
    cudaMemcpyAsync(pfeat + (size_t)NPIX * 128, ptsf, (size_t)NPTS * 128 * sizeof(float),
                    cudaMemcpyDeviceToDevice);

    pt_wid_kernel<<<32, 256>>>(ptsuv);
    win_build_kernel<<<4, 1024>>>();

    // conv_in: feat[0:8192] = Aimg @ wci^T + b   (M=8192, N=128, K=256)
    bfgemm<<<dim3(2, 64), 256>>>(pAimg, pwh + WOFF_CI, pwl + WOFF_CI, bci, pfeat, 128, 256);
    // qkv: all 16384 tokens (M=16384, N=384, K=128)
    bfgemm<<<dim3(6, 128), 256>>>(pfeat, pwh + WOFF_QKV, pwl + WOFF_QKV, bqkv, pqkv, 384, 128);
    // attention (pixel queries only)
    attn_kernel<<<dim3(8, 128), 64>>>(pqkv, po);
    // proj: image tokens only (M=8192, N=128, K=128)
    bfgemm<<<dim3(2, 64), 256>>>(po, pwh + WOFF_PR, pwl + WOFF_PR, bpr, pimg, 128, 128);
    // fused RK4 ODE
    ode_wmma<<<128, 256, ODE_SMEM>>>(pimg, pwh + WOFF_ODE, pwl + WOFF_ODE, bode, pres);
    // conv_out (M=8192, N=256, K=128)
    bfgemm<<<dim3(4, 64), 256>>>(pres, pwh + WOFF_CO, pwl + WOFF_CO, bco, pco, 256, 128);
    transpose_out_k<<<dim3(128, 8, 2), dim3(32, 8)>>>(pco, out);
}

// round 4
// speedup vs baseline: 1.6182x; 1.2574x over previous
#include <cuda_runtime.h>
#include <cuda_bf16.h>
#include <mma.h>
#include <cstdint>

using namespace nvcuda;

#define NPIX 8192
#define NPTS 8192
#define NTOK 16384
#define NWIN 128
#define CAP  256
#define NCHUNK 32

// ---------------- scratch (device globals; no allocation) ----------------
__device__ float g_feat[NTOK * 128];
__device__ float g_qkv [NTOK * 384];
__device__ float g_o   [NPIX * 128];
__device__ float g_img [NPIX * 128];
__device__ float g_res [NPIX * 128];
__device__ __nv_bfloat16 g_wh[147456];   // hi parts: ci|qkv|pr|ode|co
__device__ __nv_bfloat16 g_wl[147456];   // lo parts
__device__ int   g_ptw [NPTS];
__device__ int   g_hist[NCHUNK * NWIN];
__device__ int   g_base[NCHUNK * NWIN];
__device__ int   g_win_tok[NWIN * CAP];
__device__ int   g_win_cnt[NWIN];

#define WOFF_CI  0
#define WOFF_QKV 32768
#define WOFF_PR  81920
#define WOFF_ODE 98304
#define WOFF_CO  114688

// ---------------- bf16 pack helpers ----------------
__device__ __forceinline__ uint32_t bf16x2_of(float hi, float lo) {
    uint32_t r; asm("cvt.rn.bf16x2.f32 %0, %1, %2;" : "=r"(r) : "f"(hi), "f"(lo)); return r;
}
__device__ __forceinline__ float bf16lo_f(uint32_t v) { return __uint_as_float(v << 16); }
__device__ __forceinline__ float bf16hi_f(uint32_t v) { return __uint_as_float(v & 0xffff0000u); }

// ---------------- weight hi/lo split ----------------
__global__ void split_weights(const float* __restrict__ wci, const float* __restrict__ wqkv,
                              const float* __restrict__ wpr, const float* __restrict__ wode,
                              const float* __restrict__ wco) {
    int i = blockIdx.x * 256 + threadIdx.x;
    if (i >= 147456) return;
    float x;
    if (i < WOFF_QKV)      x = wci [i];
    else if (i < WOFF_PR)  x = wqkv[i - WOFF_QKV];
    else if (i < WOFF_ODE) x = wpr [i - WOFF_PR];
    else if (i < WOFF_CO)  x = wode[i - WOFF_ODE];
    else                   x = wco [i - WOFF_CO];
    __nv_bfloat16 h = __float2bfloat16(x);
    g_wh[i] = h;
    g_wl[i] = __float2bfloat16(x - __bfloat162float(h));
}

// ============================================================================
// Window build: deterministic 3-pass rank pipeline (replaces 117us scan)
// ============================================================================
// Pass 1: wid per point + per-chunk histogram; also fill pixel token slots.
__global__ void pt_wid_hist(const int* __restrict__ uv) {
    __shared__ int cnt[NWIN];
    int t = threadIdx.x;
    int i = blockIdx.x * 256 + t;
    if (t < NWIN) cnt[t] = 0;
    __syncthreads();
    // point wid
    int b = uv[3 * i] & 1;
    int u = uv[3 * i + 1] & 63;
    int v = uv[3 * i + 2] & 63;
    int wid = ((b * 8 + (v >> 3)) << 3) + (u >> 3);
    g_ptw[i] = wid;
    atomicAdd(&cnt[wid], 1);
    // pixel token fill (slot r of window w)
    {
        int w = i >> 6, r = i & 63;
        int wb = w >> 6, wy = (w >> 3) & 7, wx = w & 7;
        int pv = wy * 8 + (r >> 3), pu = wx * 8 + (r & 7);
        g_win_tok[w * CAP + r] = wb * 4096 + pv * 64 + pu;
    }
    __syncthreads();
    if (t < NWIN) g_hist[blockIdx.x * NWIN + t] = cnt[t];
}

// Pass 2: exclusive scan across chunks per window.
__global__ void win_scan() {
    int w = threadIdx.x;
    int run = 0;
#pragma unroll
    for (int c = 0; c < NCHUNK; c++) {
        g_base[c * NWIN + w] = run;
        run += g_hist[c * NWIN + w];
    }
    int tot = 64 + run;
    g_win_cnt[w] = tot < CAP ? tot : CAP;
}

// Pass 3: scatter points to slots in exact index order.
__global__ void pt_scatter() {
    __shared__ int cnt[NWIN];
    int t = threadIdx.x;
    int lane = t & 31;
    int i = blockIdx.x * 256 + t;
    if (t < NWIN) cnt[t] = g_base[blockIdx.x * NWIN + t];
    __syncthreads();
    int wid = g_ptw[i];
    for (int wv = 0; wv < 8; wv++) {
        if ((t >> 5) == wv) {
            unsigned mask = __match_any_sync(0xffffffffu, wid);
            int prior = __popc(mask & ((1u << lane) - 1u));
            int base = cnt[wid];
            __syncwarp();
            int rank = 64 + base + prior;
            if (rank < CAP) g_win_tok[wid * CAP + rank] = NPIX + i;
            if (prior == 0) cnt[wid] = base + __popc(mask);
        }
        __syncthreads();
    }
}

// ============================================================================
// Tensor-core GEMM (row-major A): C[M][N] = A[M][K] @ B[N][K]^T + bias
// Block 128M x 64N, 8 warps (4Mx2N), bf16 hi/lo split (3 mma passes).
// ============================================================================
__global__ __launch_bounds__(256) void bfgemm(const float* __restrict__ A,
                                              const __nv_bfloat16* __restrict__ Bh,
                                              const __nv_bfloat16* __restrict__ Bl,
                                              const float* __restrict__ bias,
                                              float* __restrict__ C, int N, int K) {
    __shared__ __align__(16) __nv_bfloat16 sAh[128 * 16], sAl[128 * 16];
    __shared__ __align__(16) __nv_bfloat16 sBh[64 * 16],  sBl[64 * 16];
    __shared__ __align__(16) float scratch[128 * 64];

    const int t = threadIdx.x;
    const int w = t >> 5;
    const int row0 = blockIdx.y << 7, col0 = blockIdx.x << 6;
    const int wm = w >> 1, wn = w & 1;
    const int m0 = wm << 5, n0 = wn << 5;

    wmma::fragment<wmma::accumulator, 16, 16, 16, float> acc[2][2];
#pragma unroll
    for (int mi = 0; mi < 2; mi++)
#pragma unroll
        for (int ni = 0; ni < 2; ni++)
            wmma::fill_fragment(acc[mi][ni], 0.f);

    const uint32_t* Bh32 = (const uint32_t*)Bh;
    const uint32_t* Bl32 = (const uint32_t*)Bl;
    uint32_t* sBh32 = (uint32_t*)sBh;
    uint32_t* sBl32 = (uint32_t*)sBl;
    uint32_t* sAh32 = (uint32_t*)sAh;
    uint32_t* sAl32 = (uint32_t*)sAl;

    for (int k0 = 0; k0 < K; k0 += 16) {
#pragma unroll
        for (int i = 0; i < 2; i++) {
            int idx = t + (i << 8);
            int r = idx >> 2, c = (idx & 3) << 2;
            float4 v = *(const float4*)(A + (size_t)(row0 + r) * K + k0 + c);
            uint32_t h01 = bf16x2_of(v.y, v.x);
            uint32_t h23 = bf16x2_of(v.w, v.z);
            uint32_t l01 = bf16x2_of(v.y - bf16hi_f(h01), v.x - bf16lo_f(h01));
            uint32_t l23 = bf16x2_of(v.w - bf16hi_f(h23), v.z - bf16lo_f(h23));
            sAh32[(r << 3) + (c >> 1)]     = h01;
            sAh32[(r << 3) + (c >> 1) + 1] = h23;
            sAl32[(r << 3) + (c >> 1)]     = l01;
            sAl32[(r << 3) + (c >> 1) + 1] = l23;
        }
#pragma unroll
        for (int i = 0; i < 2; i++) {
            int idx = t + (i << 8);
            int r = idx >> 3, c2 = idx & 7;
            size_t g = (size_t)(col0 + r) * (K >> 1) + (k0 >> 1) + c2;
            sBh32[(r << 3) + c2] = Bh32[g];
            sBl32[(r << 3) + c2] = Bl32[g];
        }
        __syncthreads();

        wmma::fragment<wmma::matrix_a, 16, 16, 16, __nv_bfloat16, wmma::row_major> ah0, ah1, al0, al1;
        wmma::fragment<wmma::matrix_b, 16, 16, 16, __nv_bfloat16, wmma::col_major> bh0, bh1, bl0, bl1;
        wmma::load_matrix_sync(ah0, sAh + (size_t)m0 * 16, 16);
        wmma::load_matrix_sync(ah1, sAh + (size_t)(m0 + 16) * 16, 16);
        wmma::load_matrix_sync(al0, sAl + (size_t)m0 * 16, 16);
        wmma::load_matrix_sync(al1, sAl + (size_t)(m0 + 16) * 16, 16);
        wmma::load_matrix_sync(bh0, sBh + (size_t)n0 * 16, 16);
        wmma::load_matrix_sync(bh1, sBh + (size_t)(n0 + 16) * 16, 16);
        wmma::load_matrix_sync(bl0, sBl + (size_t)n0 * 16, 16);
        wmma::load_matrix_sync(bl1, sBl + (size_t)(n0 + 16) * 16, 16);

        wmma::mma_sync(acc[0][0], ah0, bh0, acc[0][0]);
        wmma::mma_sync(acc[0][1], ah0, bh1, acc[0][1]);
        wmma::mma_sync(acc[1][0], ah1, bh0, acc[1][0]);
        wmma::mma_sync(acc[1][1], ah1, bh1, acc[1][1]);
        wmma::mma_sync(acc[0][0], ah0, bl0, acc[0][0]);
        wmma::mma_sync(acc[0][1], ah0, bl1, acc[0][1]);
        wmma::mma_sync(acc[1][0], ah1, bl0, acc[1][0]);
        wmma::mma_sync(acc[1][1], ah1, bl1, acc[1][1]);
        wmma::mma_sync(acc[0][0], al0, bh0, acc[0][0]);
        wmma::mma_sync(acc[0][1], al0, bh1, acc[0][1]);
        wmma::mma_sync(acc[1][0], al1, bh0, acc[1][0]);
        wmma::mma_sync(acc[1][1], al1, bh1, acc[1][1]);
        __syncthreads();
    }

#pragma unroll
    for (int mi = 0; mi < 2; mi++)
#pragma unroll
        for (int ni = 0; ni < 2; ni++)
            wmma::store_matrix_sync(scratch + (size_t)(m0 + mi * 16) * 64 + n0 + ni * 16,
                                    acc[mi][ni], 64, wmma::mem_row_major);
    __syncthreads();

    int r = t >> 1, cc = (t & 1) << 5;
#pragma unroll
    for (int q = 0; q < 8; q++) {
        float4 v = *(float4*)(scratch + r * 64 + cc + q * 4);
        float4 b = *(const float4*)(bias + col0 + cc + q * 4);
        v.x += b.x; v.y += b.y; v.z += b.z; v.w += b.w;
        *(float4*)(C + (size_t)(row0 + r) * N + col0 + cc + q * 4) = v;
    }
}

// ============================================================================
// conv_in GEMM: A read directly from NCHW image (K-major -> col_major A frags)
//   out[p][n] = sum_c img[b][c][hw] * Wci[n][c],  M=8192, K=256, N=128
// ============================================================================
__global__ __launch_bounds__(256) void bfgemm_ca(const float* __restrict__ img,
                                                 const __nv_bfloat16* __restrict__ Bh,
                                                 const __nv_bfloat16* __restrict__ Bl,
                                                 const float* __restrict__ bias,
                                                 float* __restrict__ C, int N, int K) {
    __shared__ __align__(16) __nv_bfloat16 sAh[16 * 136], sAl[16 * 136];
    __shared__ __align__(16) __nv_bfloat16 sBh[64 * 16],  sBl[64 * 16];
    __shared__ __align__(16) float scratch[128 * 64];

    const int t = threadIdx.x;
    const int w = t >> 5;
    const int row0 = blockIdx.y << 7, col0 = blockIdx.x << 6;
    const int b = row0 >> 12, hw0 = row0 & 4095;
    const int wm = w >> 1, wn = w & 1;
    const int m0 = wm << 5, n0 = wn << 5;

    wmma::fragment<wmma::accumulator, 16, 16, 16, float> acc[2][2];
#pragma unroll
    for (int mi = 0; mi < 2; mi++)
#pragma unroll
        for (int ni = 0; ni < 2; ni++)
            wmma::fill_fragment(acc[mi][ni], 0.f);

    const uint32_t* Bh32 = (const uint32_t*)Bh;
    const uint32_t* Bl32 = (const uint32_t*)Bl;
    uint32_t* sBh32 = (uint32_t*)sBh;
    uint32_t* sBl32 = (uint32_t*)sBl;
    uint32_t* sAh32 = (uint32_t*)sAh;
    uint32_t* sAl32 = (uint32_t*)sAl;

    for (int k0 = 0; k0 < K; k0 += 16) {
        // A tile: 16 k-rows x 128 pixels, coalesced from NCHW
#pragma unroll
        for (int i = 0; i < 2; i++) {
            int idx = t + (i << 8);
            int kk = idx >> 5, m4 = (idx & 31) << 2;
            float4 v = *(const float4*)(img + (size_t)b * 1048576 + (size_t)(k0 + kk) * 4096 + hw0 + m4);
            uint32_t h01 = bf16x2_of(v.y, v.x);
            uint32_t h23 = bf16x2_of(v.w, v.z);
            uint32_t l01 = bf16x2_of(v.y - bf16hi_f(h01), v.x - bf16lo_f(h01));
            uint32_t l23 = bf16x2_of(v.w - bf16hi_f(h23), v.z - bf16lo_f(h23));
            int so = kk * 68 + (m4 >> 1);
            sAh32[so] = h01; sAh32[so + 1] = h23;
            sAl32[so] = l01; sAl32[so + 1] = l23;
        }
#pragma unroll
        for (int i = 0; i < 2; i++) {
            int idx = t + (i << 8);
            int r = idx >> 3, c2 = idx & 7;
            size_t g = (size_t)(col0 + r) * (K >> 1) + (k0 >> 1) + c2;
            sBh32[(r << 3) + c2] = Bh32[g];
            sBl32[(r << 3) + c2] = Bl32[g];
        }
        __syncthreads();

        wmma::fragment<wmma::matrix_a, 16, 16, 16, __nv_bfloat16, wmma::col_major> ah0, ah1, al0, al1;
        wmma::fragment<wmma::matrix_b, 16, 16, 16, __nv_bfloat16, wmma::col_major> bh0, bh1, bl0, bl1;
        wmma::load_matrix_sync(ah0, sAh + m0, 136);
        wmma::load_matrix_sync(ah1, sAh + m0 + 16, 136);
        wmma::load_matrix_sync(al0, sAl + m0, 136);
        wmma::load_matrix_sync(al1, sAl + m0 + 16, 136);
        wmma::load_matrix_sync(bh0, sBh + (size_t)n0 * 16, 16);
        wmma::load_matrix_sync(bh1, sBh + (size_t)(n0 + 16) * 16, 16);
        wmma::load_matrix_sync(bl0, sBl + (size_t)n0 * 16, 16);
        wmma::load_matrix_sync(bl1, sBl + (size_t)(n0 + 16) * 16, 16);

        wmma::mma_sync(acc[0][0], ah0, bh0, acc[0][0]);
        wmma::mma_sync(acc[0][1], ah0, bh1, acc[0][1]);
        wmma::mma_sync(acc[1][0], ah1, bh0, acc[1][0]);
        wmma::mma_sync(acc[1][1], ah1, bh1, acc[1][1]);
        wmma::mma_sync(acc[0][0], ah0, bl0, acc[0][0]);
        wmma::mma_sync(acc[0][1], ah0, bl1, acc[0][1]);
        wmma::mma_sync(acc[1][0], ah1, bl0, acc[1][0]);
        wmma::mma_sync(acc[1][1], ah1, bl1, acc[1][1]);
        wmma::mma_sync(acc[0][0], al0, bh0, acc[0][0]);
        wmma::mma_sync(acc[0][1], al0, bh1, acc[0][1]);
        wmma::mma_sync(acc[1][0], al1, bh0, acc[1][0]);
        wmma::mma_sync(acc[1][1], al1, bh1, acc[1][1]);
        __syncthreads();
    }

#pragma unroll
    for (int mi = 0; mi < 2; mi++)
#pragma unroll
        for (int ni = 0; ni < 2; ni++)
            wmma::store_matrix_sync(scratch + (size_t)(m0 + mi * 16) * 64 + n0 + ni * 16,
                                    acc[mi][ni], 64, wmma::mem_row_major);
    __syncthreads();

    int r = t >> 1, cc = (t & 1) << 5;
#pragma unroll
    for (int q = 0; q < 8; q++) {
        float4 v = *(float4*)(scratch + r * 64 + cc + q * 4);
        float4 bb = *(const float4*)(bias + col0 + cc + q * 4);
        v.x += bb.x; v.y += bb.y; v.z += bb.z; v.w += bb.w;
        *(float4*)(C + (size_t)(row0 + r) * N + col0 + cc + q * 4) = v;
    }
}

// ============================================================================
// conv_out GEMM: stores transposed directly to NCHW output.
//   out[b][col0+n][hw0+m] = sum_k res[p][k] * Wco[n][k] + bias[n]
// ============================================================================
__global__ __launch_bounds__(256) void bfgemm_tr(const float* __restrict__ A,
                                                 const __nv_bfloat16* __restrict__ Bh,
                                                 const __nv_bfloat16* __restrict__ Bl,
                                                 const float* __restrict__ bias,
                                                 float* __restrict__ out, int K) {
    __shared__ __align__(16) __nv_bfloat16 sAh[128 * 16], sAl[128 * 16];
    __shared__ __align__(16) __nv_bfloat16 sBh[64 * 16],  sBl[64 * 16];
    __shared__ __align__(16) float scratch[64 * 132];

    const int t = threadIdx.x;
    const int w = t >> 5;
    const int row0 = blockIdx.y << 7, col0 = blockIdx.x << 6;
    const int b = row0 >> 12, hw0 = row0 & 4095;
    const int wm = w >> 1, wn = w & 1;
    const int m0 = wm << 5, n0 = wn << 5;

    wmma::fragment<wmma::accumulator, 16, 16, 16, float> acc[2][2];
#pragma unroll
    for (int mi = 0; mi < 2; mi++)
#pragma unroll
        for (int ni = 0; ni < 2; ni++)
            wmma::fill_fragment(acc[mi][ni], 0.f);

    const uint32_t* Bh32 = (const uint32_t*)Bh;
    const uint32_t* Bl32 = (const uint32_t*)Bl;
    uint32_t* sBh32 = (uint32_t*)sBh;
    uint32_t* sBl32 = (uint32_t*)sBl;
    uint32_t* sAh32 = (uint32_t*)sAh;
    uint32_t* sAl32 = (uint32_t*)sAl;

    for (int k0 = 0; k0 < K; k0 += 16) {
#pragma unroll
        for (int i = 0; i < 2; i++) {
            int idx = t + (i << 8);
            int r = idx >> 2, c = (idx & 3) << 2;
            float4 v = *(const float4*)(A + (size_t)(row0 + r) * K + k0 + c);
            uint32_t h01 = bf16x2_of(v.y, v.x);
            uint32_t h23 = bf16x2_of(v.w, v.z);
            uint32_t l01 = bf16x2_of(v.y - bf16hi_f(h01), v.x - bf16lo_f(h01));
            uint32_t l23 = bf16x2_of(v.w - bf16hi_f(h23), v.z - bf16lo_f(h23));
            sAh32[(r << 3) + (c >> 1)]     = h01;
            sAh32[(r << 3) + (c >> 1) + 1] = h23;
            sAl32[(r << 3) + (c >> 1)]     = l01;
            sAl32[(r << 3) + (c >> 1) + 1] = l23;
        }
#pragma unroll
        for (int i = 0; i < 2; i++) {
            int idx = t + (i << 8);
            int r = idx >> 3, c2 = idx & 7;
            size_t g = (size_t)(col0 + r) * (K >> 1) + (k0 >> 1) + c2;
            sBh32[(r << 3) + c2] = Bh32[g];
            sBl32[(r << 3) + c2] = Bl32[g];
        }
        __syncthreads();

        wmma::fragment<wmma::matrix_a, 16, 16, 16, __nv_bfloat16, wmma::row_major> ah0, ah1, al0, al1;
        wmma::fragment<wmma::matrix_b, 16, 16, 16, __nv_bfloat16, wmma::col_major> bh0, bh1, bl0, bl1;
        wmma::load_matrix_sync(ah0, sAh + (size_t)m0 * 16, 16);
        wmma::load_matrix_sync(ah1, sAh + (size_t)(m0 + 16) * 16, 16);
        wmma::load_matrix_sync(al0, sAl + (size_t)m0 * 16, 16);
        wmma::load_matrix_sync(al1, sAl + (size_t)(m0 + 16) * 16, 16);
        wmma::load_matrix_sync(bh0, sBh + (size_t)n0 * 16, 16);
        wmma::load_matrix_sync(bh1, sBh + (size_t)(n0 + 16) * 16, 16);
        wmma::load_matrix_sync(bl0, sBl + (size_t)n0 * 16, 16);
        wmma::load_matrix_sync(bl1, sBl + (size_t)(n0 + 16) * 16, 16);

        wmma::mma_sync(acc[0][0], ah0, bh0, acc[0][0]);
        wmma::mma_sync(acc[0][1], ah0, bh1, acc[0][1]);
        wmma::mma_sync(acc[1][0], ah1, bh0, acc[1][0]);
        wmma::mma_sync(acc[1][1], ah1, bh1, acc[1][1]);
        wmma::mma_sync(acc[0][0], ah0, bl0, acc[0][0]);
        wmma::mma_sync(acc[0][1], ah0, bl1, acc[0][1]);
        wmma::mma_sync(acc[1][0], ah1, bl0, acc[1][0]);
        wmma::mma_sync(acc[1][1], ah1, bl1, acc[1][1]);
        wmma::mma_sync(acc[0][0], al0, bh0, acc[0][0]);
        wmma::mma_sync(acc[0][1], al0, bh1, acc[0][1]);
        wmma::mma_sync(acc[1][0], al1, bh0, acc[1][0]);
        wmma::mma_sync(acc[1][1], al1, bh1, acc[1][1]);
        __syncthreads();
    }

    // store col-major: scratch[n][m], pitch 132 over m
#pragma unroll
    for (int mi = 0; mi < 2; mi++)
#pragma unroll
        for (int ni = 0; ni < 2; ni++)
            wmma::store_matrix_sync(scratch + (size_t)(n0 + ni * 16) * 132 + m0 + mi * 16,
                                    acc[mi][ni], 132, wmma::mem_col_major);
    __syncthreads();

    // epilogue: coalesced transposed store to NCHW
    const int lane = t & 31;
#pragma unroll
    for (int nn = 0; nn < 8; nn++) {
        int n = (w << 3) + nn;
        float bv = bias[col0 + n];
        float* orow = out + (size_t)b * 1048576 + (size_t)(col0 + n) * 4096 + hw0;
#pragma unroll
        for (int it = 0; it < 4; it++) {
            int m = (it << 5) + lane;
            orow[m] = scratch[n * 132 + m] + bv;
        }
    }
}

// ---------------- windowed attention (fp32, online softmax) ----------------
__global__ __launch_bounds__(64) void attn_kernel(const float* __restrict__ qkv,
                                                  float* __restrict__ o_out) {
    const int h = blockIdx.x, w = blockIdx.y;
    __shared__ float4 sK[CAP][4];
    __shared__ float4 sV[CAP][4];
    const int t = threadIdx.x;
    const int T = g_win_cnt[w];
    const int* wt = &g_win_tok[w * CAP];
    for (int j = t; j < T; j += 64) {
        int tok = wt[j];
        const float4* kp = (const float4*)(qkv + (size_t)tok * 384 + 128 + h * 16);
        const float4* vp = (const float4*)(qkv + (size_t)tok * 384 + 256 + h * 16);
        sK[j][0] = kp[0]; sK[j][1] = kp[1]; sK[j][2] = kp[2]; sK[j][3] = kp[3];
        sV[j][0] = vp[0]; sV[j][1] = vp[1]; sV[j][2] = vp[2]; sV[j][3] = vp[3];
    }
    __syncthreads();
    int qtok = wt[t];
    const float4* qp = (const float4*)(qkv + (size_t)qtok * 384 + h * 16);
    float4 q0 = qp[0], q1 = qp[1], q2 = qp[2], q3 = qp[3];
    float m = -1e30f, l = 0.f;
    float4 o0 = {0,0,0,0}, o1 = {0,0,0,0}, o2 = {0,0,0,0}, o3 = {0,0,0,0};
    for (int j = 0; j < T; j++) {
        float4 k0 = sK[j][0], k1 = sK[j][1], k2 = sK[j][2], k3 = sK[j][3];
        float s = q0.x*k0.x + q0.y*k0.y + q0.z*k0.z + q0.w*k0.w
                + q1.x*k1.x + q1.y*k1.y + q1.z*k1.z + q1.w*k1.w
                + q2.x*k2.x + q2.y*k2.y + q2.z*k2.z + q2.w*k2.w
                + q3.x*k3.x + q3.y*k3.y + q3.z*k3.z + q3.w*k3.w;
        s *= 0.25f;
        float mn = fmaxf(m, s);
        float sc = __expf(m - mn);
        float p  = __expf(s - mn);
        l = l * sc + p;
        float4 v0 = sV[j][0], v1 = sV[j][1], v2 = sV[j][2], v3 = sV[j][3];
        o0.x = o0.x*sc + p*v0.x; o0.y = o0.y*sc + p*v0.y; o0.z = o0.z*sc + p*v0.z; o0.w = o0.w*sc + p*v0.w;
        o1.x = o1.x*sc + p*v1.x; o1.y = o1.y*sc + p*v1.y; o1.z = o1.z*sc + p*v1.z; o1.w = o1.w*sc + p*v1.w;
        o2.x = o2.x*sc + p*v2.x; o2.y = o2.y*sc + p*v2.y; o2.z = o2.z*sc + p*v2.z; o2.w = o2.w*sc + p*v2.w;
        o3.x = o3.x*sc + p*v3.x; o3.y = o3.y*sc + p*v3.y; o3.z = o3.z*sc + p*v3.z; o3.w = o3.w*sc + p*v3.w;
        m = mn;
    }
    float inv = 1.f / l;
    float* op = o_out + (size_t)qtok * 128 + h * 16;
    ((float4*)op)[0] = make_float4(o0.x*inv, o0.y*inv, o0.z*inv, o0.w*inv);
    ((float4*)op)[1] = make_float4(o1.x*inv, o1.y*inv, o1.z*inv, o1.w*inv);
    ((float4*)op)[2] = make_float4(o2.x*inv, o2.y*inv, o2.z*inv, o2.w*inv);
    ((float4*)op)[3] = make_float4(o3.x*inv, o3.y*inv, o3.z*inv, o3.w*inv);
}

// ============================================================================
// Fused RK4 ODE on wmma bf16 hi/lo (unchanged from R3)
// ============================================================================
#define ODE_SMEM 137728

__global__ __launch_bounds__(256, 1) void ode_wmma(const float* __restrict__ img,
                                                   const __nv_bfloat16* __restrict__ Wh_g,
                                                   const __nv_bfloat16* __restrict__ Wl_g,
                                                   const float* __restrict__ bias,
                                                   float* __restrict__ res) {
    extern __shared__ __align__(16) char sm[];
    float* scratch = (float*)sm;
    float* sBias   = (float*)(sm + 32768);
    __nv_bfloat16* sWh = (__nv_bfloat16*)(sm + 33280);
    __nv_bfloat16* sWl = (__nv_bfloat16*)(sm + 68096);
    __nv_bfloat16* sZh = (__nv_bfloat16*)(sm + 102912);
    __nv_bfloat16* sZl = (__nv_bfloat16*)(sm + 120320);

    const int t = threadIdx.x;
    const int w = t >> 5;
    const int row0 = blockIdx.x << 6;

    const uint32_t* wh32 = (const uint32_t*)Wh_g;
    const uint32_t* wl32 = (const uint32_t*)Wl_g;
    uint32_t* sWh32 = (uint32_t*)sWh;
    uint32_t* sWl32 = (uint32_t*)sWl;
    for (int idx = t; idx < 8192; idx += 256) {
        int n = idx >> 6, c2 = idx & 63;
        sWh32[n * 68 + c2] = wh32[idx];
        sWl32[n * 68 + c2] = wl32[idx];
    }
    if (t < 128) sBias[t] = bias[t];

    const int r = t >> 2, c0 = (t & 3) << 5;
    float y[32], accv[32];
#pragma unroll
    for (int q = 0; q < 8; q++) {
        float4 v = *(const float4*)(img + (size_t)(row0 + r) * 128 + c0 + q * 4);
        y[q*4] = v.x; y[q*4+1] = v.y; y[q*4+2] = v.z; y[q*4+3] = v.w;
    }
    uint32_t* zh32 = (uint32_t*)(sZh + r * 136 + c0);
    uint32_t* zl32 = (uint32_t*)(sZl + r * 136 + c0);
#pragma unroll
    for (int j = 0; j < 16; j++) {
        float x0 = y[2*j], x1 = y[2*j+1];
        uint32_t h = bf16x2_of(x1, x0);
        zh32[j] = h;
        zl32[j] = bf16x2_of(x1 - bf16hi_f(h), x0 - bf16lo_f(h));
    }
    __syncthreads();

    const int wm = w >> 2, wn = w & 3;
    const int m0 = wm << 5, n0 = wn << 5;

    for (int ev = 0; ev < 16; ev++) {
        wmma::fragment<wmma::accumulator, 16, 16, 16, float> acc[2][2];
#pragma unroll
        for (int mi = 0; mi < 2; mi++)
#pragma unroll
            for (int ni = 0; ni < 2; ni++)
                wmma::fill_fragment(acc[mi][ni], 0.f);

#pragma unroll
        for (int k = 0; k < 8; k++) {
            wmma::fragment<wmma::matrix_a, 16, 16, 16, __nv_bfloat16, wmma::row_major> ah0, ah1, al0, al1;
            wmma::fragment<wmma::matrix_b, 16, 16, 16, __nv_bfloat16, wmma::col_major> bh0, bh1, bl0, bl1;
            wmma::load_matrix_sync(ah0, sZh + (size_t)m0 * 136 + k * 16, 136);
            wmma::load_matrix_sync(ah1, sZh + (size_t)(m0 + 16) * 136 + k * 16, 136);
            wmma::load_matrix_sync(al0, sZl + (size_t)m0 * 136 + k * 16, 136);
            wmma::load_matrix_sync(al1, sZl + (size_t)(m0 + 16) * 136 + k * 16, 136);
            wmma::load_matrix_sync(bh0, sWh + (size_t)n0 * 136 + k * 16, 136);
            wmma::load_matrix_sync(bh1, sWh + (size_t)(n0 + 16) * 136 + k * 16, 136);
            wmma::load_matrix_sync(bl0, sWl + (size_t)n0 * 136 + k * 16, 136);
            wmma::load_matrix_sync(bl1, sWl + (size_t)(n0 + 16) * 136 + k * 16, 136);

            wmma::mma_sync(acc[0][0], ah0, bh0, acc[0][0]);
            wmma::mma_sync(acc[0][1], ah0, bh1, acc[0][1]);
            wmma::mma_sync(acc[1][0], ah1, bh0, acc[1][0]);
            wmma::mma_sync(acc[1][1], ah1, bh1, acc[1][1]);
            wmma::mma_sync(acc[0][0], ah0, bl0, acc[0][0]);
            wmma::mma_sync(acc[0][1], ah0, bl1, acc[0][1]);
            wmma::mma_sync(acc[1][0], ah1, bl0, acc[1][0]);
            wmma::mma_sync(acc[1][1], ah1, bl1, acc[1][1]);
            wmma::mma_sync(acc[0][0], al0, bh0, acc[0][0]);
            wmma::mma_sync(acc[0][1], al0, bh1, acc[0][1]);
            wmma::mma_sync(acc[1][0], al1, bh0, acc[1][0]);
            wmma::mma_sync(acc[1][1], al1, bh1, acc[1][1]);
        }
#pragma unroll
        for (int mi = 0; mi < 2; mi++)
#pragma unroll
            for (int ni = 0; ni < 2; ni++)
                wmma::store_matrix_sync(scratch + (size_t)(m0 + mi * 16) * 128 + n0 + ni * 16,
                                        acc[mi][ni], 128, wmma::mem_row_major);
        __syncthreads();

        const int st = ev & 3;
        const float zc = (st < 2) ? 0.125f : 0.25f;
        const float aw = (st == 1 || st == 2) ? 2.f : 1.f;
#pragma unroll
        for (int j = 0; j < 16; j++) {
            float k0f = fmaxf(scratch[r * 128 + c0 + 2*j]     + sBias[c0 + 2*j],     0.f);
            float k1f = fmaxf(scratch[r * 128 + c0 + 2*j + 1] + sBias[c0 + 2*j + 1], 0.f);
            float a0 = (st == 0) ? k0f : accv[2*j]     + aw * k0f;
            float a1 = (st == 0) ? k1f : accv[2*j + 1] + aw * k1f;
            accv[2*j] = a0; accv[2*j+1] = a1;
            float z0, z1;
            if (st < 3) { z0 = y[2*j] + zc * k0f; z1 = y[2*j+1] + zc * k1f; }
            else {
                y[2*j]   += (1.f / 24.f) * a0;
                y[2*j+1] += (1.f / 24.f) * a1;
                z0 = y[2*j]; z1 = y[2*j+1];
            }
            uint32_t h = bf16x2_of(z1, z0);
            zh32[j] = h;
            zl32[j] = bf16x2_of(z1 - bf16hi_f(h), z0 - bf16lo_f(h));
        }
        __syncthreads();
    }

#pragma unroll
    for (int q = 0; q < 8; q++) {
        float4 v = *(const float4*)(img + (size_t)(row0 + r) * 128 + c0 + q * 4);
        v.x += y[q*4]; v.y += y[q*4+1]; v.z += y[q*4+2]; v.w += y[q*4+3];
        *(float4*)(res + (size_t)(row0 + r) * 128 + c0 + q * 4) = v;
    }
}

// ---------------- launch ----------------
extern "C" void kernel_launch(void* const* d_in, const int* in_sizes, int n_in,
                              void* d_out, int out_size) {
    const float* img   = (const float*)d_in[0];
    const int*   ptsuv = (const int*)  d_in[1];
    const float* ptsf  = (const float*)d_in[2];
    const float* wci   = (const float*)d_in[3];
    const float* bci   = (const float*)d_in[4];
    const float* wqkv  = (const float*)d_in[5];
    const float* bqkv  = (const float*)d_in[6];
    const float* wpr   = (const float*)d_in[7];
    const float* bpr   = (const float*)d_in[8];
    const float* wode  = (const float*)d_in[9];
    const float* bode  = (const float*)d_in[10];
    const float* wco   = (const float*)d_in[11];
    const float* bco   = (const float*)d_in[12];
    float* out = (float*)d_out;

    float *pfeat, *pqkv, *po, *pimg, *pres;
    __nv_bfloat16 *pwh, *pwl;
    cudaGetSymbolAddress((void**)&pfeat, g_feat);
    cudaGetSymbolAddress((void**)&pqkv,  g_qkv);
    cudaGetSymbolAddress((void**)&po,    g_o);
    cudaGetSymbolAddress((void**)&pimg,  g_img);
    cudaGetSymbolAddress((void**)&pres,  g_res);
    cudaGetSymbolAddress((void**)&pwh,   g_wh);
    cudaGetSymbolAddress((void**)&pwl,   g_wl);

    cudaFuncSetAttribute(ode_wmma, cudaFuncAttributeMaxDynamicSharedMemorySize, ODE_SMEM);

    split_weights<<<576, 256>>>(wci, wqkv, wpr, wode, wco);
    cudaMemcpyAsync(pfeat + (size_t)NPIX * 128, ptsf, (size_t)NPTS * 128 * sizeof(float),
                    cudaMemcpyDeviceToDevice);

    // window build (deterministic 3-pass)
    pt_wid_hist<<<NCHUNK, 256>>>(ptsuv);
    win_scan<<<1, 128>>>();
    pt_scatter<<<NCHUNK, 256>>>();

    // conv_in straight from NCHW: M=8192, N=128, K=256
    bfgemm_ca<<<dim3(2, 64), 256>>>(img, pwh + WOFF_CI, pwl + WOFF_CI, bci, pfeat, 128, 256);
    // qkv: Q only for pixel tokens (M=8192,N=128), K+V for all (M=16384,N=256)
    bfgemm<<<dim3(2, 64), 256>>>(pfeat, pwh + WOFF_QKV, pwl + WOFF_QKV, bqkv, pqkv, 384, 128);
    bfgemm<<<dim3(4, 128), 256>>>(pfeat, pwh + WOFF_QKV + 128 * 128, pwl + WOFF_QKV + 128 * 128,
                                  bqkv + 128, pqkv + 128, 384, 128);
    // attention (pixel queries only)
    attn_kernel<<<dim3(8, 128), 64>>>(pqkv, po);
    // proj: M=8192, N=128, K=128
    bfgemm<<<dim3(2, 64), 256>>>(po, pwh + WOFF_PR, pwl + WOFF_PR, bpr, pimg, 128, 128);
    // fused RK4 ODE
    ode_wmma<<<128, 256, ODE_SMEM>>>(pimg, pwh + WOFF_ODE, pwl + WOFF_ODE, bode, pres);
    // conv_out with fused transpose to NCHW: M=8192, N=256, K=128
    bfgemm_tr<<<dim3(4, 64), 256>>>(pres, pwh + WOFF_CO, pwl + WOFF_CO, bco, out, 128);
}